// round 4
// baseline (speedup 1.0000x reference)
#include <cuda_runtime.h>
#include <cuda_bf16.h>
#include <math.h>
#include <stdint.h>

#define H 1024
#define BB 16384
#define NSTEPS 8
#define NBIG 8192  // [ op1(1024) | num1(1024) | gi r,z,n (3072) | gh r,z,n (3072) ]

// GEMM tiling
#define BM 128
#define BN 128
#define BK 32
#define STAGES 3
#define TILE_BYTES 8192            // one operand tile (128 rows x 32 bf16)
#define STAGE_BYTES (4 * TILE_BYTES)
#define GEMM_SMEM (STAGES * STAGE_BYTES)   // 98304

// ---- scratch (device globals: sanctioned no-alloc workaround) ----
__device__ __nv_bfloat16 g_Bhi[(size_t)NBIG * H];   // 16 MB  W_big hi, [n][k]
__device__ __nv_bfloat16 g_Blo[(size_t)NBIG * H];   // 16 MB  W_big lo, [n][k]
__device__ __nv_bfloat16 g_Ahi[(size_t)BB * H];     // 32 MB  h hi
__device__ __nv_bfloat16 g_Alo[(size_t)BB * H];     // 32 MB  h lo
__device__ float g_bias[NBIG];
__device__ float g_Y[(size_t)BB * NBIG];            // 512 MB

// ================= helpers =================
__device__ __forceinline__ uint32_t smem_u32(const void* p) {
    uint32_t a;
    asm("{ .reg .u64 t; cvta.to.shared.u64 t, %1; cvt.u32.u64 %0, t; }" : "=r"(a) : "l"(p));
    return a;
}
__device__ __forceinline__ void cpasync16(uint32_t s, const void* g) {
    asm volatile("cp.async.cg.shared.global [%0], [%1], 16;" :: "r"(s), "l"(g) : "memory");
}
__device__ __forceinline__ void cp_commit() {
    asm volatile("cp.async.commit_group;" ::: "memory");
}
__device__ __forceinline__ void cp_wait1() {
    asm volatile("cp.async.wait_group 1;" ::: "memory");
}
__device__ __forceinline__ void cp_wait0() {
    asm volatile("cp.async.wait_group 0;" ::: "memory");
}
__device__ __forceinline__ void ldsm4(uint32_t a, uint32_t& r0, uint32_t& r1, uint32_t& r2, uint32_t& r3) {
    asm volatile("ldmatrix.sync.aligned.m8n8.x4.shared.b16 {%0,%1,%2,%3}, [%4];"
                 : "=r"(r0), "=r"(r1), "=r"(r2), "=r"(r3) : "r"(a));
}
__device__ __forceinline__ void mma16816(float* c, const uint32_t* a, const uint32_t* b) {
    asm volatile("mma.sync.aligned.m16n8k16.row.col.f32.bf16.bf16.f32 "
                 "{%0,%1,%2,%3}, {%4,%5,%6,%7}, {%8,%9}, {%0,%1,%2,%3};"
                 : "+f"(c[0]), "+f"(c[1]), "+f"(c[2]), "+f"(c[3])
                 : "r"(a[0]), "r"(a[1]), "r"(a[2]), "r"(a[3]), "r"(b[0]), "r"(b[1]));
}
// swizzled byte offset within one 128x32-bf16 tile (64B rows, 4x16B units)
__device__ __forceinline__ uint32_t SW(uint32_t row, uint32_t u) {
    return row * 64u + ((u ^ ((row >> 1) & 3u)) << 4);
}
__device__ __forceinline__ float gelu_f(float x) {
    return 0.5f * x * (1.0f + erff(x * 0.70710678118654752440f));
}
__device__ __forceinline__ float sigmoid_f(float x) {
    return 1.0f / (1.0f + expf(-x));
}

// ================= prep: split weights to bf16 hi/lo in [n][k] layout =================
__global__ void prep_kernel(const float* __restrict__ w_op1, const float* __restrict__ b_op1,
                            const float* __restrict__ w_num1, const float* __restrict__ b_num1,
                            const float* __restrict__ w_ih, const float* __restrict__ b_ih,
                            const float* __restrict__ w_hh, const float* __restrict__ b_hh) {
    int idx = blockIdx.x * blockDim.x + threadIdx.x;
    if (idx >= NBIG * H) return;
    int n = idx >> 10;
    int k = idx & 1023;
    float v;
    if (n < 1024)       v = w_op1[k * H + n];
    else if (n < 2048)  v = w_num1[k * H + (n - 1024)];
    else if (n < 5120)  v = w_ih[(size_t)(n - 2048) * H + k];
    else                v = w_hh[(size_t)(n - 5120) * H + k];
    __nv_bfloat16 hi = __float2bfloat16(v);
    __nv_bfloat16 lo = __float2bfloat16(v - __bfloat162float(hi));
    g_Bhi[idx] = hi;
    g_Blo[idx] = lo;
    if (k == 0) {
        float bb;
        if (n < 1024)       bb = b_op1[n];
        else if (n < 2048)  bb = b_num1[n - 1024];
        else if (n < 5120)  bb = b_ih[n - 2048];
        else                bb = b_hh[n - 5120];
        g_bias[n] = bb;
    }
}

// ================= per-step: split h to bf16 hi/lo =================
__global__ __launch_bounds__(256) void convert_h_kernel(const float* __restrict__ h) {
    int idx = blockIdx.x * blockDim.x + threadIdx.x;   // over BB*H/4
    float4 v = *(const float4*)(h + (size_t)idx * 4);
    __nv_bfloat16 h0 = __float2bfloat16(v.x);
    __nv_bfloat16 h1 = __float2bfloat16(v.y);
    __nv_bfloat16 h2 = __float2bfloat16(v.z);
    __nv_bfloat16 h3 = __float2bfloat16(v.w);
    __nv_bfloat162 p0 = __halves2bfloat162(h0, h1);
    __nv_bfloat162 p1 = __halves2bfloat162(h2, h3);
    *(uint2*)(g_Ahi + (size_t)idx * 4) =
        make_uint2(*(uint32_t*)&p0, *(uint32_t*)&p1);
    __nv_bfloat16 l0 = __float2bfloat16(v.x - __bfloat162float(h0));
    __nv_bfloat16 l1 = __float2bfloat16(v.y - __bfloat162float(h1));
    __nv_bfloat16 l2 = __float2bfloat16(v.z - __bfloat162float(h2));
    __nv_bfloat16 l3 = __float2bfloat16(v.w - __bfloat162float(h3));
    __nv_bfloat162 q0 = __halves2bfloat162(l0, l1);
    __nv_bfloat162 q1 = __halves2bfloat162(l2, l3);
    *(uint2*)(g_Alo + (size_t)idx * 4) =
        make_uint2(*(uint32_t*)&q0, *(uint32_t*)&q1);
}

// ================= mma.sync GEMM: g_Y = h @ W_big + bias =================
__global__ __launch_bounds__(256, 2) void gemm_mma_kernel() {
    extern __shared__ char smem[];
    uint32_t sb = smem_u32(smem);
    int tid = threadIdx.x;
    int lane = tid & 31;
    int wid = tid >> 5;
    int warp_m = wid & 1;     // 2 warps in M -> 64 rows each
    int warp_n = wid >> 1;    // 4 warps in N -> 32 cols each
    int m0 = blockIdx.y * BM;
    int n0 = blockIdx.x * BN;

    // ---- g2s mapping: per array, each thread covers rows (tid>>2) and (tid>>2)+64 at unit tid&3
    int row0 = tid >> 2;
    int u0 = tid & 3;
    uint32_t so0 = SW(row0, u0);
    uint32_t so1 = SW(row0 + 64, u0);
    const __nv_bfloat16* pAhi0 = g_Ahi + (size_t)(m0 + row0) * H + u0 * 8;
    const __nv_bfloat16* pAhi1 = pAhi0 + (size_t)64 * H;
    const __nv_bfloat16* pAlo0 = g_Alo + (size_t)(m0 + row0) * H + u0 * 8;
    const __nv_bfloat16* pAlo1 = pAlo0 + (size_t)64 * H;
    const __nv_bfloat16* pBhi0 = g_Bhi + (size_t)(n0 + row0) * H + u0 * 8;
    const __nv_bfloat16* pBhi1 = pBhi0 + (size_t)64 * H;
    const __nv_bfloat16* pBlo0 = g_Blo + (size_t)(n0 + row0) * H + u0 * 8;
    const __nv_bfloat16* pBlo1 = pBlo0 + (size_t)64 * H;

    // ---- ldmatrix offsets (within a tile) ----
    uint32_t offA[4][2], offB[2][2];
    {
        uint32_t r = (uint32_t)(warp_m * 64 + (lane & 15));
        #pragma unroll
        for (int mi = 0; mi < 4; mi++)
            #pragma unroll
            for (int ks = 0; ks < 2; ks++)
                offA[mi][ks] = SW(r + mi * 16, (uint32_t)(ks * 2 + (lane >> 4)));
        uint32_t rb = (uint32_t)(warp_n * 32 + (lane & 7) + ((lane >> 4) << 3));
        #pragma unroll
        for (int nj2 = 0; nj2 < 2; nj2++)
            #pragma unroll
            for (int ks = 0; ks < 2; ks++)
                offB[nj2][ks] = SW(rb + nj2 * 16, (uint32_t)(ks * 2 + ((lane >> 3) & 1)));
    }

    float acc[4][4][4];
    #pragma unroll
    for (int i = 0; i < 4; i++)
        #pragma unroll
        for (int j = 0; j < 4; j++)
            #pragma unroll
            for (int r = 0; r < 4; r++) acc[i][j][r] = 0.f;

    // ---- pipeline ----
    #define ISSUE(kb, stg) do {                                                    \
        uint32_t base = sb + (stg) * STAGE_BYTES;                                  \
        int ko = (kb) * BK;                                                        \
        cpasync16(base + so0,                    pAhi0 + ko);                      \
        cpasync16(base + so1,                    pAhi1 + ko);                      \
        cpasync16(base + TILE_BYTES + so0,       pAlo0 + ko);                      \
        cpasync16(base + TILE_BYTES + so1,       pAlo1 + ko);                      \
        cpasync16(base + 2 * TILE_BYTES + so0,   pBhi0 + ko);                      \
        cpasync16(base + 2 * TILE_BYTES + so1,   pBhi1 + ko);                      \
        cpasync16(base + 3 * TILE_BYTES + so0,   pBlo0 + ko);                      \
        cpasync16(base + 3 * TILE_BYTES + so1,   pBlo1 + ko);                      \
        cp_commit();                                                               \
    } while (0)

    ISSUE(0, 0);
    ISSUE(1, 1);

    const int NKB = H / BK;   // 32
    for (int kb = 0; kb < NKB; kb++) {
        if (kb < NKB - 2) cp_wait1(); else cp_wait0();
        __syncthreads();

        uint32_t base = sb + (uint32_t)(kb % STAGES) * STAGE_BYTES;
        uint32_t sAhi = base, sAlo = base + TILE_BYTES;
        uint32_t sBhi = base + 2 * TILE_BYTES, sBlo = base + 3 * TILE_BYTES;

        #pragma unroll
        for (int ks = 0; ks < 2; ks++) {
            uint32_t Af[4][4], Bh[4][2], Bl[4][2];
            #pragma unroll
            for (int nj2 = 0; nj2 < 2; nj2++) {
                ldsm4(sBhi + offB[nj2][ks], Bh[nj2 * 2][0], Bh[nj2 * 2][1],
                      Bh[nj2 * 2 + 1][0], Bh[nj2 * 2 + 1][1]);
                ldsm4(sBlo + offB[nj2][ks], Bl[nj2 * 2][0], Bl[nj2 * 2][1],
                      Bl[nj2 * 2 + 1][0], Bl[nj2 * 2 + 1][1]);
            }
            #pragma unroll
            for (int mi = 0; mi < 4; mi++)
                ldsm4(sAhi + offA[mi][ks], Af[mi][0], Af[mi][1], Af[mi][2], Af[mi][3]);
            #pragma unroll
            for (int mi = 0; mi < 4; mi++)
                #pragma unroll
                for (int nj = 0; nj < 4; nj++) {
                    mma16816(acc[mi][nj], Af[mi], Bh[nj]);   // hi*hi
                    mma16816(acc[mi][nj], Af[mi], Bl[nj]);   // hi*lo
                }
            #pragma unroll
            for (int mi = 0; mi < 4; mi++)
                ldsm4(sAlo + offA[mi][ks], Af[mi][0], Af[mi][1], Af[mi][2], Af[mi][3]);
            #pragma unroll
            for (int mi = 0; mi < 4; mi++)
                #pragma unroll
                for (int nj = 0; nj < 4; nj++)
                    mma16816(acc[mi][nj], Af[mi], Bh[nj]);   // lo*hi
        }
        __syncthreads();
        if (kb + 2 < NKB) ISSUE(kb + 2, (kb + 2) % STAGES);
    }

    // ---- epilogue: write Y with bias (direct gmem stores) ----
    #pragma unroll
    for (int nj = 0; nj < 4; nj++) {
        int n = n0 + warp_n * 32 + nj * 8 + (lane & 3) * 2;
        float2 b2 = *(const float2*)&g_bias[n];
        #pragma unroll
        for (int mi = 0; mi < 4; mi++) {
            int m = m0 + warp_m * 64 + mi * 16 + (lane >> 2);
            float2 v0 = make_float2(acc[mi][nj][0] + b2.x, acc[mi][nj][1] + b2.y);
            float2 v1 = make_float2(acc[mi][nj][2] + b2.x, acc[mi][nj][3] + b2.y);
            *(float2*)(g_Y + (size_t)m * NBIG + n) = v0;
            *(float2*)(g_Y + (size_t)(m + 8) * NBIG + n) = v1;
        }
    }
}

// ================= heads =================
__global__ __launch_bounds__(256) void heads_kernel(
    const float* __restrict__ w_op2, const float* __restrict__ b_op2,
    const float* __restrict__ w_num2, const float* __restrict__ b_num2,
    float* __restrict__ ops, float* __restrict__ nums)
{
    __shared__ float s_w2[H * 5];
    __shared__ float s_wn[H];
    int tid = threadIdx.x;
    for (int i = tid; i < H * 5; i += 256) s_w2[i] = w_op2[i];
    for (int i = tid; i < H; i += 256)     s_wn[i] = w_num2[i];
    __syncthreads();

    int warp = tid >> 5, lane = tid & 31;
    int b = blockIdx.x * 8 + warp;
    const float* Yr = g_Y + (size_t)b * NBIG;

    float a0 = 0.f, a1 = 0.f, a2 = 0.f, a3 = 0.f, a4 = 0.f, an = 0.f;
    for (int j = lane; j < H; j += 32) {
        float g = gelu_f(Yr[j]);
        a0 += g * s_w2[j * 5 + 0];
        a1 += g * s_w2[j * 5 + 1];
        a2 += g * s_w2[j * 5 + 2];
        a3 += g * s_w2[j * 5 + 3];
        a4 += g * s_w2[j * 5 + 4];
        float gn = gelu_f(Yr[H + j]);
        an += gn * s_wn[j];
    }
    #pragma unroll
    for (int off = 16; off > 0; off >>= 1) {
        a0 += __shfl_xor_sync(0xffffffffu, a0, off);
        a1 += __shfl_xor_sync(0xffffffffu, a1, off);
        a2 += __shfl_xor_sync(0xffffffffu, a2, off);
        a3 += __shfl_xor_sync(0xffffffffu, a3, off);
        a4 += __shfl_xor_sync(0xffffffffu, a4, off);
        an += __shfl_xor_sync(0xffffffffu, an, off);
    }
    if (lane == 0) {
        float* o = ops + (size_t)b * 5;
        o[0] = a0 + b_op2[0];
        o[1] = a1 + b_op2[1];
        o[2] = a2 + b_op2[2];
        o[3] = a3 + b_op2[3];
        o[4] = a4 + b_op2[4];
        nums[b] = an + b_num2[0];
    }
}

// ================= GRU elementwise =================
__global__ void gru_kernel(const float* __restrict__ hin, float* __restrict__ hout) {
    int idx = blockIdx.x * blockDim.x + threadIdx.x;
    int b = idx >> 10;
    int j = idx & 1023;
    const float* Yr = g_Y + (size_t)b * NBIG;
    float ir = Yr[2048 + j];
    float iz = Yr[3072 + j];
    float in_ = Yr[4096 + j];
    float hr = Yr[5120 + j];
    float hz = Yr[6144 + j];
    float hn = Yr[7168 + j];
    float h = hin[idx];
    float r = sigmoid_f(ir + hr);
    float z = sigmoid_f(iz + hz);
    float n = tanhf(in_ + r * hn);
    hout[idx] = (1.0f - z) * n + z * h;
}

extern "C" void kernel_launch(void* const* d_in, const int* in_sizes, int n_in,
                              void* d_out, int out_size) {
    const float* x      = (const float*)d_in[0];
    const float* w_op1  = (const float*)d_in[2];
    const float* b_op1  = (const float*)d_in[3];
    const float* w_op2  = (const float*)d_in[4];
    const float* b_op2  = (const float*)d_in[5];
    const float* w_num1 = (const float*)d_in[6];
    const float* b_num1 = (const float*)d_in[7];
    const float* w_num2 = (const float*)d_in[8];
    const float* b_num2 = (const float*)d_in[9];
    const float* w_ih   = (const float*)d_in[10];
    const float* b_ih   = (const float*)d_in[11];
    const float* w_hh   = (const float*)d_in[12];
    const float* b_hh   = (const float*)d_in[13];

    float* out = (float*)d_out;
    float* final_state = out;                       // [B,H]
    float* ops    = out + (size_t)BB * H;           // [8,B,5]
    float* nums   = ops + (size_t)NSTEPS * BB * 5;  // [8,B,1]
    float* states = nums + (size_t)NSTEPS * BB;     // [8,B,H]

    cudaFuncSetAttribute(gemm_mma_kernel, cudaFuncAttributeMaxDynamicSharedMemorySize, GEMM_SMEM);

    prep_kernel<<<(NBIG * H + 255) / 256, 256>>>(w_op1, b_op1, w_num1, b_num1,
                                                 w_ih, b_ih, w_hh, b_hh);
    cudaMemcpyAsync(states, x, (size_t)BB * H * sizeof(float), cudaMemcpyDeviceToDevice);

    for (int s = 0; s < NSTEPS; s++) {
        const float* h = states + (size_t)s * BB * H;
        float* hnext = (s < NSTEPS - 1) ? states + (size_t)(s + 1) * BB * H : final_state;

        convert_h_kernel<<<(BB * H / 4) / 256, 256>>>(h);
        dim3 grid(NBIG / BN, BB / BM);
        gemm_mma_kernel<<<grid, 256, GEMM_SMEM>>>();
        heads_kernel<<<BB / 8, 256>>>(w_op2, b_op2, w_num2, b_num2,
                                      ops + (size_t)s * BB * 5, nums + (size_t)s * BB);
        gru_kernel<<<(BB * H) / 256, 256>>>(h, hnext);
    }
}

// round 5
// speedup vs baseline: 1.8181x; 1.8181x over previous
#include <cuda_runtime.h>
#include <cuda_fp16.h>
#include <math.h>
#include <stdint.h>

#define H 1024
#define BB 16384
#define NSTEPS 8
// fused N layout: [ op1:0 | num1:1024 | r:2048 | z:3072 | i_n:4096 | h_n:5120 ] -> 6144
#define NB 6144

// GEMM tiling
#define BM 128
#define BN 128
#define BK 32
#define STAGES 3
#define TILE_B 8192                 // one operand tile (128 rows x 32 fp16)
#define STAGE_B (3 * TILE_B)        // A | Bhi | Blo
#define GEMM_SMEM (STAGES * STAGE_B)   // 73728

// ---- scratch (device globals: sanctioned no-alloc workaround) ----
__device__ __half g_Bhi[(size_t)NB * H];    // 12 MB  W_big hi, [n][k]
__device__ __half g_Blo[(size_t)NB * H];    // 12 MB  W_big lo, [n][k]
__device__ __half g_A[(size_t)BB * H];      // 32 MB  h (fp16)
__device__ float g_bias[NB];
__device__ float g_Y[(size_t)BB * NB];      // 384 MB

// ================= helpers =================
__device__ __forceinline__ uint32_t smem_u32(const void* p) {
    uint32_t a;
    asm("{ .reg .u64 t; cvta.to.shared.u64 t, %1; cvt.u32.u64 %0, t; }" : "=r"(a) : "l"(p));
    return a;
}
__device__ __forceinline__ void cpasync16(uint32_t s, const void* g) {
    asm volatile("cp.async.cg.shared.global [%0], [%1], 16;" :: "r"(s), "l"(g) : "memory");
}
__device__ __forceinline__ void cp_commit() {
    asm volatile("cp.async.commit_group;" ::: "memory");
}
__device__ __forceinline__ void cp_wait1() {
    asm volatile("cp.async.wait_group 1;" ::: "memory");
}
__device__ __forceinline__ void cp_wait0() {
    asm volatile("cp.async.wait_group 0;" ::: "memory");
}
__device__ __forceinline__ void ldsm4(uint32_t a, uint32_t& r0, uint32_t& r1, uint32_t& r2, uint32_t& r3) {
    asm volatile("ldmatrix.sync.aligned.m8n8.x4.shared.b16 {%0,%1,%2,%3}, [%4];"
                 : "=r"(r0), "=r"(r1), "=r"(r2), "=r"(r3) : "r"(a));
}
__device__ __forceinline__ void mma16816(float* c, const uint32_t* a, const uint32_t* b) {
    asm volatile("mma.sync.aligned.m16n8k16.row.col.f32.f16.f16.f32 "
                 "{%0,%1,%2,%3}, {%4,%5,%6,%7}, {%8,%9}, {%0,%1,%2,%3};"
                 : "+f"(c[0]), "+f"(c[1]), "+f"(c[2]), "+f"(c[3])
                 : "r"(a[0]), "r"(a[1]), "r"(a[2]), "r"(a[3]), "r"(b[0]), "r"(b[1]));
}
// swizzled byte offset within one 128x32-fp16 tile (64B rows, 4x16B units)
__device__ __forceinline__ uint32_t SW(uint32_t row, uint32_t u) {
    return row * 64u + ((u ^ ((row >> 1) & 3u)) << 4);
}
__device__ __forceinline__ float gelu_f(float x) {
    return 0.5f * x * (1.0f + erff(x * 0.70710678118654752440f));
}
__device__ __forceinline__ float sigmoid_f(float x) {
    return 1.0f / (1.0f + expf(-x));
}
__device__ __forceinline__ uint32_t pkh2(float a, float b) {
    __half2 t = __floats2half2_rn(a, b);
    return *reinterpret_cast<uint32_t*>(&t);
}

// ================= prep: fused+merged weights -> fp16 hi/lo, [n][k] =================
__global__ void prep_kernel(const float* __restrict__ w_op1, const float* __restrict__ b_op1,
                            const float* __restrict__ w_num1, const float* __restrict__ b_num1,
                            const float* __restrict__ w_ih, const float* __restrict__ b_ih,
                            const float* __restrict__ w_hh, const float* __restrict__ b_hh) {
    int idx = blockIdx.x * blockDim.x + threadIdx.x;
    if (idx >= NB * H) return;
    int n = idx >> 10;
    int k = idx & 1023;
    float v;
    if (n < 1024)       v = w_op1[k * H + n];
    else if (n < 2048)  v = w_num1[k * H + (n - 1024)];
    else if (n < 4096) { int j = n - 2048; v = w_ih[(size_t)j * H + k] + w_hh[(size_t)j * H + k]; }
    else if (n < 5120) { int j = n - 4096 + 2048; v = w_ih[(size_t)j * H + k]; }
    else               { int j = n - 5120 + 2048; v = w_hh[(size_t)j * H + k]; }
    __half hi = __float2half(v);
    __half lo = __float2half(v - __half2float(hi));
    g_Bhi[idx] = hi;
    g_Blo[idx] = lo;
    if (k == 0) {
        float bb;
        if (n < 1024)       bb = b_op1[n];
        else if (n < 2048)  bb = b_num1[n - 1024];
        else if (n < 4096)  bb = b_ih[n - 2048] + b_hh[n - 2048];
        else if (n < 5120)  bb = b_ih[n - 4096 + 2048];
        else                bb = b_hh[n - 5120 + 2048];
        g_bias[n] = bb;
    }
}

// ================= initial: x -> fp16 A =================
__global__ __launch_bounds__(256) void convert_x_kernel(const float* __restrict__ x) {
    int idx = blockIdx.x * blockDim.x + threadIdx.x;   // over BB*H/4
    float4 v = *(const float4*)(x + (size_t)idx * 4);
    *(uint2*)(g_A + (size_t)idx * 4) = make_uint2(pkh2(v.x, v.y), pkh2(v.z, v.w));
}

// ================= mma.sync GEMM: g_Y = h @ W_big + bias =================
__global__ __launch_bounds__(256, 2) void gemm_mma_kernel() {
    extern __shared__ char smem[];
    uint32_t sb = smem_u32(smem);
    int tid = threadIdx.x;
    int lane = tid & 31;
    int wid = tid >> 5;
    int warp_m = wid & 1;     // 2 warps in M -> 64 rows each
    int warp_n = wid >> 1;    // 4 warps in N -> 32 cols each
    int m0 = blockIdx.y * BM;
    int n0 = blockIdx.x * BN;

    // g2s: per array each thread covers rows (tid>>2), (tid>>2)+64 at 16B unit tid&3
    int row0 = tid >> 2;
    int u0 = tid & 3;
    uint32_t so0 = SW(row0, u0);
    uint32_t so1 = SW(row0 + 64, u0);
    const __half* pA0 = g_A + (size_t)(m0 + row0) * H + u0 * 8;
    const __half* pA1 = pA0 + (size_t)64 * H;
    const __half* pBh0 = g_Bhi + (size_t)(n0 + row0) * H + u0 * 8;
    const __half* pBh1 = pBh0 + (size_t)64 * H;
    const __half* pBl0 = g_Blo + (size_t)(n0 + row0) * H + u0 * 8;
    const __half* pBl1 = pBl0 + (size_t)64 * H;

    // ldmatrix offsets within a tile
    uint32_t offA[4][2], offB[2][2];
    {
        uint32_t r = (uint32_t)(warp_m * 64 + (lane & 15));
        #pragma unroll
        for (int mi = 0; mi < 4; mi++)
            #pragma unroll
            for (int ks = 0; ks < 2; ks++)
                offA[mi][ks] = SW(r + mi * 16, (uint32_t)(ks * 2 + (lane >> 4)));
        uint32_t rb = (uint32_t)(warp_n * 32 + (lane & 7) + ((lane >> 4) << 3));
        #pragma unroll
        for (int nj2 = 0; nj2 < 2; nj2++)
            #pragma unroll
            for (int ks = 0; ks < 2; ks++)
                offB[nj2][ks] = SW(rb + nj2 * 16, (uint32_t)(ks * 2 + ((lane >> 3) & 1)));
    }

    float acc[4][4][4];
    #pragma unroll
    for (int i = 0; i < 4; i++)
        #pragma unroll
        for (int j = 0; j < 4; j++)
            #pragma unroll
            for (int r = 0; r < 4; r++) acc[i][j][r] = 0.f;

    #define ISSUE(kb, stg) do {                                                   \
        uint32_t base = sb + (stg) * STAGE_B;                                     \
        int ko = (kb) * BK;                                                       \
        cpasync16(base + so0,                pA0 + ko);                           \
        cpasync16(base + so1,                pA1 + ko);                           \
        cpasync16(base + TILE_B + so0,       pBh0 + ko);                          \
        cpasync16(base + TILE_B + so1,       pBh1 + ko);                          \
        cpasync16(base + 2 * TILE_B + so0,   pBl0 + ko);                          \
        cpasync16(base + 2 * TILE_B + so1,   pBl1 + ko);                          \
        cp_commit();                                                              \
    } while (0)

    ISSUE(0, 0);
    ISSUE(1, 1);

    const int NKB = H / BK;   // 32
    for (int kb = 0; kb < NKB; kb++) {
        if (kb < NKB - 2) cp_wait1(); else cp_wait0();
        __syncthreads();

        uint32_t base = sb + (uint32_t)(kb % STAGES) * STAGE_B;
        uint32_t sA = base, sBh = base + TILE_B, sBl = base + 2 * TILE_B;

        #pragma unroll
        for (int ks = 0; ks < 2; ks++) {
            uint32_t Af[4][4], Bh[4][2], Bl[4][2];
            #pragma unroll
            for (int nj2 = 0; nj2 < 2; nj2++) {
                ldsm4(sBh + offB[nj2][ks], Bh[nj2 * 2][0], Bh[nj2 * 2][1],
                      Bh[nj2 * 2 + 1][0], Bh[nj2 * 2 + 1][1]);
                ldsm4(sBl + offB[nj2][ks], Bl[nj2 * 2][0], Bl[nj2 * 2][1],
                      Bl[nj2 * 2 + 1][0], Bl[nj2 * 2 + 1][1]);
            }
            #pragma unroll
            for (int mi = 0; mi < 4; mi++)
                ldsm4(sA + offA[mi][ks], Af[mi][0], Af[mi][1], Af[mi][2], Af[mi][3]);
            #pragma unroll
            for (int mi = 0; mi < 4; mi++)
                #pragma unroll
                for (int nj = 0; nj < 4; nj++) {
                    mma16816(acc[mi][nj], Af[mi], Bh[nj]);   // A * W_hi
                    mma16816(acc[mi][nj], Af[mi], Bl[nj]);   // A * W_lo
                }
        }
        __syncthreads();
        if (kb + 2 < NKB) ISSUE(kb + 2, (kb + 2) % STAGES);
    }

    // epilogue: write Y with bias
    #pragma unroll
    for (int nj = 0; nj < 4; nj++) {
        int n = n0 + warp_n * 32 + nj * 8 + (lane & 3) * 2;
        float2 b2 = *(const float2*)&g_bias[n];
        #pragma unroll
        for (int mi = 0; mi < 4; mi++) {
            int m = m0 + warp_m * 64 + mi * 16 + (lane >> 2);
            float2 v0 = make_float2(acc[mi][nj][0] + b2.x, acc[mi][nj][1] + b2.y);
            float2 v1 = make_float2(acc[mi][nj][2] + b2.x, acc[mi][nj][3] + b2.y);
            *(float2*)(g_Y + (size_t)m * NB + n) = v0;
            *(float2*)(g_Y + (size_t)(m + 8) * NB + n) = v1;
        }
    }
}

// ================= heads =================
__global__ __launch_bounds__(256) void heads_kernel(
    const float* __restrict__ w_op2, const float* __restrict__ b_op2,
    const float* __restrict__ w_num2, const float* __restrict__ b_num2,
    float* __restrict__ ops, float* __restrict__ nums)
{
    __shared__ float s_w2[H * 5];
    __shared__ float s_wn[H];
    int tid = threadIdx.x;
    for (int i = tid; i < H * 5; i += 256) s_w2[i] = w_op2[i];
    for (int i = tid; i < H; i += 256)     s_wn[i] = w_num2[i];
    __syncthreads();

    int warp = tid >> 5, lane = tid & 31;
    int b = blockIdx.x * 8 + warp;
    const float* Yr = g_Y + (size_t)b * NB;

    float a0 = 0.f, a1 = 0.f, a2 = 0.f, a3 = 0.f, a4 = 0.f, an = 0.f;
    for (int j = lane; j < H; j += 32) {
        float g = gelu_f(Yr[j]);
        a0 += g * s_w2[j * 5 + 0];
        a1 += g * s_w2[j * 5 + 1];
        a2 += g * s_w2[j * 5 + 2];
        a3 += g * s_w2[j * 5 + 3];
        a4 += g * s_w2[j * 5 + 4];
        float gn = gelu_f(Yr[H + j]);
        an += gn * s_wn[j];
    }
    #pragma unroll
    for (int off = 16; off > 0; off >>= 1) {
        a0 += __shfl_xor_sync(0xffffffffu, a0, off);
        a1 += __shfl_xor_sync(0xffffffffu, a1, off);
        a2 += __shfl_xor_sync(0xffffffffu, a2, off);
        a3 += __shfl_xor_sync(0xffffffffu, a3, off);
        a4 += __shfl_xor_sync(0xffffffffu, a4, off);
        an += __shfl_xor_sync(0xffffffffu, an, off);
    }
    if (lane == 0) {
        float* o = ops + (size_t)b * 5;
        o[0] = a0 + b_op2[0];
        o[1] = a1 + b_op2[1];
        o[2] = a2 + b_op2[2];
        o[3] = a3 + b_op2[3];
        o[4] = a4 + b_op2[4];
        nums[b] = an + b_num2[0];
    }
}

// ================= GRU elementwise (fused: writes h' fp32 AND fp16 for next GEMM) =======
__global__ __launch_bounds__(256) void gru_kernel(const float* __restrict__ hin,
                                                  float* __restrict__ hout) {
    int t = blockIdx.x * blockDim.x + threadIdx.x;   // over BB*H/4
    int b = t >> 8;            // H/4 = 256 per row
    int j = (t & 255) * 4;
    const float* Yr = g_Y + (size_t)b * NB;
    float4 rv = *(const float4*)(Yr + 2048 + j);
    float4 zv = *(const float4*)(Yr + 3072 + j);
    float4 iv = *(const float4*)(Yr + 4096 + j);
    float4 nv = *(const float4*)(Yr + 5120 + j);
    float4 h4 = *(const float4*)(hin + (size_t)t * 4);

    float r0 = sigmoid_f(rv.x), r1 = sigmoid_f(rv.y), r2 = sigmoid_f(rv.z), r3 = sigmoid_f(rv.w);
    float z0 = sigmoid_f(zv.x), z1 = sigmoid_f(zv.y), z2 = sigmoid_f(zv.z), z3 = sigmoid_f(zv.w);
    float n0 = tanhf(iv.x + r0 * nv.x);
    float n1 = tanhf(iv.y + r1 * nv.y);
    float n2 = tanhf(iv.z + r2 * nv.z);
    float n3 = tanhf(iv.w + r3 * nv.w);
    float4 o;
    o.x = (1.f - z0) * n0 + z0 * h4.x;
    o.y = (1.f - z1) * n1 + z1 * h4.y;
    o.z = (1.f - z2) * n2 + z2 * h4.z;
    o.w = (1.f - z3) * n3 + z3 * h4.w;
    *(float4*)(hout + (size_t)t * 4) = o;
    *(uint2*)(g_A + (size_t)t * 4) = make_uint2(pkh2(o.x, o.y), pkh2(o.z, o.w));
}

extern "C" void kernel_launch(void* const* d_in, const int* in_sizes, int n_in,
                              void* d_out, int out_size) {
    const float* x      = (const float*)d_in[0];
    const float* w_op1  = (const float*)d_in[2];
    const float* b_op1  = (const float*)d_in[3];
    const float* w_op2  = (const float*)d_in[4];
    const float* b_op2  = (const float*)d_in[5];
    const float* w_num1 = (const float*)d_in[6];
    const float* b_num1 = (const float*)d_in[7];
    const float* w_num2 = (const float*)d_in[8];
    const float* b_num2 = (const float*)d_in[9];
    const float* w_ih   = (const float*)d_in[10];
    const float* b_ih   = (const float*)d_in[11];
    const float* w_hh   = (const float*)d_in[12];
    const float* b_hh   = (const float*)d_in[13];

    float* out = (float*)d_out;
    float* final_state = out;                       // [B,H]
    float* ops    = out + (size_t)BB * H;           // [8,B,5]
    float* nums   = ops + (size_t)NSTEPS * BB * 5;  // [8,B,1]
    float* states = nums + (size_t)NSTEPS * BB;     // [8,B,H]

    cudaFuncSetAttribute(gemm_mma_kernel, cudaFuncAttributeMaxDynamicSharedMemorySize, GEMM_SMEM);

    prep_kernel<<<(NB * H + 255) / 256, 256>>>(w_op1, b_op1, w_num1, b_num1,
                                               w_ih, b_ih, w_hh, b_hh);
    convert_x_kernel<<<(BB * H / 4) / 256, 256>>>(x);
    cudaMemcpyAsync(states, x, (size_t)BB * H * sizeof(float), cudaMemcpyDeviceToDevice);

    for (int s = 0; s < NSTEPS; s++) {
        const float* h = states + (size_t)s * BB * H;
        float* hnext = (s < NSTEPS - 1) ? states + (size_t)(s + 1) * BB * H : final_state;

        dim3 grid(NB / BN, BB / BM);
        gemm_mma_kernel<<<grid, 256, GEMM_SMEM>>>();
        heads_kernel<<<BB / 8, 256>>>(w_op2, b_op2, w_num2, b_num2,
                                      ops + (size_t)s * BB * 5, nums + (size_t)s * BB);
        gru_kernel<<<(BB * H / 4) / 256, 256>>>(h, hnext);
    }
}

// round 7
// speedup vs baseline: 3.1530x; 1.7342x over previous
#include <cuda_runtime.h>
#include <cuda_fp16.h>
#include <math.h>
#include <stdint.h>

#define H 1024
#define BB 16384
#define NSTEPS 8
// fused N layout: [ op1:0 | num1:1024 | r:2048 | z:3072 | i_n:4096 | h_n:5120 ] -> 6144
#define NB 6144

// GEMM tiling
#define BM 128
#define BN 128
#define BK 64
#define STAGES 3
#define TILE_B 16384                // one operand tile (128 rows x 64 fp16)
#define STAGE_B (2 * TILE_B)        // A | B
#define GEMM_SMEM (STAGES * STAGE_B)   // 98304

// ---- scratch (device globals: sanctioned no-alloc workaround) ----
__device__ __half g_B[(size_t)NB * H];      // 12 MB  W_big fp16, [n][k]
__device__ __half g_A[(size_t)BB * H];      // 32 MB  h (fp16)
__device__ float g_bias[NB];
__device__ float g_Y[(size_t)BB * NB];      // 384 MB

// ================= helpers =================
__device__ __forceinline__ uint32_t smem_u32(const void* p) {
    uint32_t a;
    asm("{ .reg .u64 t; cvta.to.shared.u64 t, %1; cvt.u32.u64 %0, t; }" : "=r"(a) : "l"(p));
    return a;
}
__device__ __forceinline__ void cpasync16(uint32_t s, const void* g) {
    asm volatile("cp.async.cg.shared.global [%0], [%1], 16;" :: "r"(s), "l"(g) : "memory");
}
__device__ __forceinline__ void cp_commit() {
    asm volatile("cp.async.commit_group;" ::: "memory");
}
__device__ __forceinline__ void cp_wait1() {
    asm volatile("cp.async.wait_group 1;" ::: "memory");
}
__device__ __forceinline__ void cp_wait0() {
    asm volatile("cp.async.wait_group 0;" ::: "memory");
}
__device__ __forceinline__ void ldsm4(uint32_t a, uint32_t& r0, uint32_t& r1, uint32_t& r2, uint32_t& r3) {
    asm volatile("ldmatrix.sync.aligned.m8n8.x4.shared.b16 {%0,%1,%2,%3}, [%4];"
                 : "=r"(r0), "=r"(r1), "=r"(r2), "=r"(r3) : "r"(a));
}
__device__ __forceinline__ void mma16816(float* c, const uint32_t* a, const uint32_t* b) {
    asm volatile("mma.sync.aligned.m16n8k16.row.col.f32.f16.f16.f32 "
                 "{%0,%1,%2,%3}, {%4,%5,%6,%7}, {%8,%9}, {%0,%1,%2,%3};"
                 : "+f"(c[0]), "+f"(c[1]), "+f"(c[2]), "+f"(c[3])
                 : "r"(a[0]), "r"(a[1]), "r"(a[2]), "r"(a[3]), "r"(b[0]), "r"(b[1]));
}
// swizzled byte offset within one 128x64-fp16 tile (128B rows, 8x16B units)
__device__ __forceinline__ uint32_t SW(uint32_t row, uint32_t u) {
    return row * 128u + ((u ^ (row & 7u)) << 4);
}
__device__ __forceinline__ float gelu_f(float x) {
    return 0.5f * x * (1.0f + erff(x * 0.70710678118654752440f));
}
__device__ __forceinline__ float sigmoid_f(float x) {
    return 1.0f / (1.0f + expf(-x));
}
__device__ __forceinline__ uint32_t pkh2(float a, float b) {
    __half2 t = __floats2half2_rn(a, b);
    return *reinterpret_cast<uint32_t*>(&t);
}

// ================= prep: fused+merged weights -> fp16, [n][k] =================
__global__ void prep_kernel(const float* __restrict__ w_op1, const float* __restrict__ b_op1,
                            const float* __restrict__ w_num1, const float* __restrict__ b_num1,
                            const float* __restrict__ w_ih, const float* __restrict__ b_ih,
                            const float* __restrict__ w_hh, const float* __restrict__ b_hh) {
    int idx = blockIdx.x * blockDim.x + threadIdx.x;
    if (idx >= NB * H) return;
    int n = idx >> 10;
    int k = idx & 1023;
    float v;
    if (n < 1024)       v = w_op1[k * H + n];
    else if (n < 2048)  v = w_num1[k * H + (n - 1024)];
    else if (n < 4096) { int j = n - 2048; v = w_ih[(size_t)j * H + k] + w_hh[(size_t)j * H + k]; }
    else if (n < 5120) { int j = n - 4096 + 2048; v = w_ih[(size_t)j * H + k]; }
    else               { int j = n - 5120 + 2048; v = w_hh[(size_t)j * H + k]; }
    g_B[idx] = __float2half(v);
    if (k == 0) {
        float bb;
        if (n < 1024)       bb = b_op1[n];
        else if (n < 2048)  bb = b_num1[n - 1024];
        else if (n < 4096)  bb = b_ih[n - 2048] + b_hh[n - 2048];
        else if (n < 5120)  bb = b_ih[n - 4096 + 2048];
        else                bb = b_hh[n - 5120 + 2048];
        g_bias[n] = bb;
    }
}

// ================= initial: x -> fp16 A =================
__global__ __launch_bounds__(256) void convert_x_kernel(const float* __restrict__ x) {
    int idx = blockIdx.x * blockDim.x + threadIdx.x;   // over BB*H/4
    float4 v = *(const float4*)(x + (size_t)idx * 4);
    *(uint2*)(g_A + (size_t)idx * 4) = make_uint2(pkh2(v.x, v.y), pkh2(v.z, v.w));
}

// ================= mma.sync GEMM: g_Y = h @ W_big + bias (GELU on head cols) ======
__global__ __launch_bounds__(256, 2) void gemm_mma_kernel() {
    extern __shared__ char smem[];
    uint32_t sb = smem_u32(smem);
    int tid = threadIdx.x;
    int lane = tid & 31;
    int wid = tid >> 5;
    int warp_m = wid & 1;     // 2 warps in M -> 64 rows each
    int warp_n = wid >> 1;    // 4 warps in N -> 32 cols each
    int m0 = blockIdx.y * BM;
    int n0 = blockIdx.x * BN;

    // g2s: each thread covers rows row0+{0,32,64,96} at 16B unit u0, per array
    int row0 = tid >> 3;          // 0..31
    int u0 = tid & 7;
    uint32_t so0 = SW(row0, u0);
    uint32_t so1 = SW(row0 + 32, u0);
    uint32_t so2 = SW(row0 + 64, u0);
    uint32_t so3 = SW(row0 + 96, u0);
    const __half* pA0 = g_A + (size_t)(m0 + row0) * H + u0 * 8;
    const __half* pB0 = g_B + (size_t)(n0 + row0) * H + u0 * 8;

    // ldmatrix offset components
    uint32_t rA = (uint32_t)(warp_m * 64 + (lane & 15));
    uint32_t baseA = rA * 128u;
    uint32_t hib = (uint32_t)(lane >> 4);
    uint32_t mAx = rA & 7u;
    uint32_t rB = (uint32_t)(warp_n * 32 + (lane & 7) + ((lane >> 4) << 3));
    uint32_t baseB = rB * 128u;
    uint32_t bbit = (uint32_t)((lane >> 3) & 1);
    uint32_t mBx = rB & 7u;
    uint32_t xA[4], xB[4];
    #pragma unroll
    for (int ks = 0; ks < 4; ks++) {
        xA[ks] = (((uint32_t)(ks * 2) + hib) ^ mAx) << 4;
        xB[ks] = (((uint32_t)(ks * 2) + bbit) ^ mBx) << 4;
    }

    float acc[4][4][4];
    #pragma unroll
    for (int i = 0; i < 4; i++)
        #pragma unroll
        for (int j = 0; j < 4; j++)
            #pragma unroll
            for (int r = 0; r < 4; r++) acc[i][j][r] = 0.f;

    #define ISSUE(kb, stg) do {                                                   \
        uint32_t base = sb + (stg) * STAGE_B;                                     \
        int ko = (kb) * BK;                                                       \
        cpasync16(base + so0,          pA0 + ko);                                 \
        cpasync16(base + so1,          pA0 + (size_t)32 * H + ko);                \
        cpasync16(base + so2,          pA0 + (size_t)64 * H + ko);                \
        cpasync16(base + so3,          pA0 + (size_t)96 * H + ko);                \
        cpasync16(base + TILE_B + so0, pB0 + ko);                                 \
        cpasync16(base + TILE_B + so1, pB0 + (size_t)32 * H + ko);                \
        cpasync16(base + TILE_B + so2, pB0 + (size_t)64 * H + ko);                \
        cpasync16(base + TILE_B + so3, pB0 + (size_t)96 * H + ko);                \
        cp_commit();                                                              \
    } while (0)

    ISSUE(0, 0);
    ISSUE(1, 1);

    const int NKB = H / BK;   // 16
    for (int kb = 0; kb < NKB; kb++) {
        if (kb < NKB - 2) cp_wait1(); else cp_wait0();
        __syncthreads();

        uint32_t base = sb + (uint32_t)(kb % STAGES) * STAGE_B;
        uint32_t sA = base + baseA;
        uint32_t sB = base + TILE_B + baseB;

        #pragma unroll
        for (int ks = 0; ks < 4; ks++) {
            uint32_t Af[4][4], Bf[4][2];
            ldsm4(sB + xB[ks],         Bf[0][0], Bf[0][1], Bf[1][0], Bf[1][1]);
            ldsm4(sB + 2048 + xB[ks],  Bf[2][0], Bf[2][1], Bf[3][0], Bf[3][1]);
            #pragma unroll
            for (int mi = 0; mi < 4; mi++)
                ldsm4(sA + mi * 2048 + xA[ks], Af[mi][0], Af[mi][1], Af[mi][2], Af[mi][3]);
            #pragma unroll
            for (int mi = 0; mi < 4; mi++)
                #pragma unroll
                for (int nj = 0; nj < 4; nj++)
                    mma16816(acc[mi][nj], Af[mi], Bf[nj]);
        }
        __syncthreads();
        if (kb + 2 < NKB) ISSUE(kb + 2, (kb + 2) % STAGES);
    }

    // epilogue: +bias, GELU on head segments (uniform per CTA), write Y
    bool do_gelu = (n0 < 2048);
    #pragma unroll
    for (int nj = 0; nj < 4; nj++) {
        int n = n0 + warp_n * 32 + nj * 8 + (lane & 3) * 2;
        float2 b2 = *(const float2*)&g_bias[n];
        #pragma unroll
        for (int mi = 0; mi < 4; mi++) {
            int m = m0 + warp_m * 64 + mi * 16 + (lane >> 2);
            float v0 = acc[mi][nj][0] + b2.x;
            float v1 = acc[mi][nj][1] + b2.y;
            float v2 = acc[mi][nj][2] + b2.x;
            float v3 = acc[mi][nj][3] + b2.y;
            if (do_gelu) {
                v0 = gelu_f(v0); v1 = gelu_f(v1); v2 = gelu_f(v2); v3 = gelu_f(v3);
            }
            *(float2*)(g_Y + (size_t)m * NB + n) = make_float2(v0, v1);
            *(float2*)(g_Y + (size_t)(m + 8) * NB + n) = make_float2(v2, v3);
        }
    }
}

// ================= heads (Y head cols already GELU'd) =================
__global__ __launch_bounds__(256) void heads_kernel(
    const float* __restrict__ w_op2, const float* __restrict__ b_op2,
    const float* __restrict__ w_num2, const float* __restrict__ b_num2,
    float* __restrict__ ops, float* __restrict__ nums)
{
    __shared__ float s_w2[H * 5];
    __shared__ float s_wn[H];
    int tid = threadIdx.x;
    for (int i = tid; i < H * 5; i += 256) s_w2[i] = w_op2[i];
    for (int i = tid; i < H; i += 256)     s_wn[i] = w_num2[i];
    __syncthreads();

    int warp = tid >> 5, lane = tid & 31;
    int b = blockIdx.x * 8 + warp;
    const float* Yr = g_Y + (size_t)b * NB;

    float a0 = 0.f, a1 = 0.f, a2 = 0.f, a3 = 0.f, a4 = 0.f, an = 0.f;
    #pragma unroll
    for (int it = 0; it < 8; it++) {
        int j = lane * 4 + it * 128;
        float4 g = *(const float4*)(Yr + j);
        float4 gn = *(const float4*)(Yr + H + j);
        #pragma unroll
        for (int e = 0; e < 4; e++) {
            float gv = (&g.x)[e];
            const float* w = &s_w2[(j + e) * 5];
            a0 += gv * w[0];
            a1 += gv * w[1];
            a2 += gv * w[2];
            a3 += gv * w[3];
            a4 += gv * w[4];
            an += (&gn.x)[e] * s_wn[j + e];
        }
    }
    #pragma unroll
    for (int off = 16; off > 0; off >>= 1) {
        a0 += __shfl_xor_sync(0xffffffffu, a0, off);
        a1 += __shfl_xor_sync(0xffffffffu, a1, off);
        a2 += __shfl_xor_sync(0xffffffffu, a2, off);
        a3 += __shfl_xor_sync(0xffffffffu, a3, off);
        a4 += __shfl_xor_sync(0xffffffffu, a4, off);
        an += __shfl_xor_sync(0xffffffffu, an, off);
    }
    if (lane == 0) {
        float* o = ops + (size_t)b * 5;
        o[0] = a0 + b_op2[0];
        o[1] = a1 + b_op2[1];
        o[2] = a2 + b_op2[2];
        o[3] = a3 + b_op2[3];
        o[4] = a4 + b_op2[4];
        nums[b] = an + b_num2[0];
    }
}

// ================= GRU elementwise (also writes fp16 A for next step) =========
__global__ __launch_bounds__(256) void gru_kernel(const float* __restrict__ hin,
                                                  float* __restrict__ hout) {
    int t = blockIdx.x * blockDim.x + threadIdx.x;   // over BB*H/4
    int b = t >> 8;            // H/4 = 256 per row
    int j = (t & 255) * 4;
    const float* Yr = g_Y + (size_t)b * NB;
    float4 rv = *(const float4*)(Yr + 2048 + j);
    float4 zv = *(const float4*)(Yr + 3072 + j);
    float4 iv = *(const float4*)(Yr + 4096 + j);
    float4 nv = *(const float4*)(Yr + 5120 + j);
    float4 h4 = *(const float4*)(hin + (size_t)t * 4);

    float r0 = sigmoid_f(rv.x), r1 = sigmoid_f(rv.y), r2 = sigmoid_f(rv.z), r3 = sigmoid_f(rv.w);
    float z0 = sigmoid_f(zv.x), z1 = sigmoid_f(zv.y), z2 = sigmoid_f(zv.z), z3 = sigmoid_f(zv.w);
    float n0 = tanhf(iv.x + r0 * nv.x);
    float n1 = tanhf(iv.y + r1 * nv.y);
    float n2 = tanhf(iv.z + r2 * nv.z);
    float n3 = tanhf(iv.w + r3 * nv.w);
    float4 o;
    o.x = (1.f - z0) * n0 + z0 * h4.x;
    o.y = (1.f - z1) * n1 + z1 * h4.y;
    o.z = (1.f - z2) * n2 + z2 * h4.z;
    o.w = (1.f - z3) * n3 + z3 * h4.w;
    *(float4*)(hout + (size_t)t * 4) = o;
    *(uint2*)(g_A + (size_t)t * 4) = make_uint2(pkh2(o.x, o.y), pkh2(o.z, o.w));
}

extern "C" void kernel_launch(void* const* d_in, const int* in_sizes, int n_in,
                              void* d_out, int out_size) {
    const float* x      = (const float*)d_in[0];
    const float* w_op1  = (const float*)d_in[2];
    const float* b_op1  = (const float*)d_in[3];
    const float* w_op2  = (const float*)d_in[4];
    const float* b_op2  = (const float*)d_in[5];
    const float* w_num1 = (const float*)d_in[6];
    const float* b_num1 = (const float*)d_in[7];
    const float* w_num2 = (const float*)d_in[8];
    const float* b_num2 = (const float*)d_in[9];
    const float* w_ih   = (const float*)d_in[10];
    const float* b_ih   = (const float*)d_in[11];
    const float* w_hh   = (const float*)d_in[12];
    const float* b_hh   = (const float*)d_in[13];

    float* out = (float*)d_out;
    float* final_state = out;                       // [B,H]
    float* ops    = out + (size_t)BB * H;           // [8,B,5]
    float* nums   = ops + (size_t)NSTEPS * BB * 5;  // [8,B,1]
    float* states = nums + (size_t)NSTEPS * BB;     // [8,B,H]

    cudaFuncSetAttribute(gemm_mma_kernel, cudaFuncAttributeMaxDynamicSharedMemorySize, GEMM_SMEM);

    prep_kernel<<<(NB * H + 255) / 256, 256>>>(w_op1, b_op1, w_num1, b_num1,
                                               w_ih, b_ih, w_hh, b_hh);
    convert_x_kernel<<<(BB * H / 4) / 256, 256>>>(x);
    cudaMemcpyAsync(states, x, (size_t)BB * H * sizeof(float), cudaMemcpyDeviceToDevice);

    for (int s = 0; s < NSTEPS; s++) {
        const float* h = states + (size_t)s * BB * H;
        float* hnext = (s < NSTEPS - 1) ? states + (size_t)(s + 1) * BB * H : final_state;

        dim3 grid(NB / BN, BB / BM);
        gemm_mma_kernel<<<grid, 256, GEMM_SMEM>>>();
        heads_kernel<<<BB / 8, 256>>>(w_op2, b_op2, w_num2, b_num2,
                                      ops + (size_t)s * BB * 5, nums + (size_t)s * BB);
        gru_kernel<<<(BB * H / 4) / 256, 256>>>(h, hnext);
    }
}

// round 8
// speedup vs baseline: 3.2025x; 1.0157x over previous
#include <cuda_runtime.h>
#include <cuda_fp16.h>
#include <math.h>
#include <stdint.h>

#define H 1024
#define BB 16384
#define NSTEPS 8
// fused N layout: [ op1:0..1023 | num1:1024..2047 | gates interleaved: n=2048+4*j+g, g=(r,z,in,hn) ]
#define NB 6144

// GEMM tiling
#define BM 128
#define BN 128
#define BK 64
#define STAGES 3
#define TILE_B 16384                // one operand tile (128 rows x 64 fp16)
#define STAGE_B (2 * TILE_B)        // A | B
#define GEMM_SMEM (STAGES * STAGE_B)   // 98304

// ---- scratch (device globals: sanctioned no-alloc workaround) ----
__device__ __half g_B[(size_t)NB * H];      // 12 MB  W_big fp16, [n][k]
__device__ __half g_A0[(size_t)BB * H];     // 32 MB  h fp16 ping
__device__ __half g_A1[(size_t)BB * H];     // 32 MB  h fp16 pong
__device__ float g_bias[NB];
__device__ __half g_Yh[(size_t)BB * 2048];  // 64 MB  GELU'd head activations (fp16)

// ================= helpers =================
__device__ __forceinline__ uint32_t smem_u32(const void* p) {
    uint32_t a;
    asm("{ .reg .u64 t; cvta.to.shared.u64 t, %1; cvt.u32.u64 %0, t; }" : "=r"(a) : "l"(p));
    return a;
}
__device__ __forceinline__ void cpasync16(uint32_t s, const void* g) {
    asm volatile("cp.async.cg.shared.global [%0], [%1], 16;" :: "r"(s), "l"(g) : "memory");
}
__device__ __forceinline__ void cp_commit() {
    asm volatile("cp.async.commit_group;" ::: "memory");
}
__device__ __forceinline__ void cp_wait1() {
    asm volatile("cp.async.wait_group 1;" ::: "memory");
}
__device__ __forceinline__ void cp_wait0() {
    asm volatile("cp.async.wait_group 0;" ::: "memory");
}
__device__ __forceinline__ void ldsm4(uint32_t a, uint32_t& r0, uint32_t& r1, uint32_t& r2, uint32_t& r3) {
    asm volatile("ldmatrix.sync.aligned.m8n8.x4.shared.b16 {%0,%1,%2,%3}, [%4];"
                 : "=r"(r0), "=r"(r1), "=r"(r2), "=r"(r3) : "r"(a));
}
__device__ __forceinline__ void mma16816(float* c, const uint32_t* a, const uint32_t* b) {
    asm volatile("mma.sync.aligned.m16n8k16.row.col.f32.f16.f16.f32 "
                 "{%0,%1,%2,%3}, {%4,%5,%6,%7}, {%8,%9}, {%0,%1,%2,%3};"
                 : "+f"(c[0]), "+f"(c[1]), "+f"(c[2]), "+f"(c[3])
                 : "r"(a[0]), "r"(a[1]), "r"(a[2]), "r"(a[3]), "r"(b[0]), "r"(b[1]));
}
// swizzled byte offset within one 128x64-fp16 tile (128B rows, 8x16B units)
__device__ __forceinline__ uint32_t SW(uint32_t row, uint32_t u) {
    return row * 128u + ((u ^ (row & 7u)) << 4);
}
__device__ __forceinline__ float gelu_f(float x) {
    return 0.5f * x * (1.0f + erff(x * 0.70710678118654752440f));
}
__device__ __forceinline__ float sigmoid_f(float x) {
    return 1.0f / (1.0f + expf(-x));
}
__device__ __forceinline__ uint32_t pkh2(float a, float b) {
    __half2 t = __floats2half2_rn(a, b);
    return *reinterpret_cast<uint32_t*>(&t);
}

// ================= prep: fused weights -> fp16, [n][k], gate-interleaved =========
__global__ void prep_kernel(const float* __restrict__ w_op1, const float* __restrict__ b_op1,
                            const float* __restrict__ w_num1, const float* __restrict__ b_num1,
                            const float* __restrict__ w_ih, const float* __restrict__ b_ih,
                            const float* __restrict__ w_hh, const float* __restrict__ b_hh) {
    int idx = blockIdx.x * blockDim.x + threadIdx.x;
    if (idx >= NB * H) return;
    int n = idx >> 10;
    int k = idx & 1023;
    float v;
    float bb = 0.f;
    if (n < 1024) {
        v = w_op1[k * H + n];
        bb = b_op1[n];
    } else if (n < 2048) {
        v = w_num1[k * H + (n - 1024)];
        bb = b_num1[n - 1024];
    } else {
        int j = (n - 2048) >> 2;
        int g = n & 3;
        if (g == 0) {       // r = ih + hh (row j)
            v = w_ih[(size_t)j * H + k] + w_hh[(size_t)j * H + k];
            bb = b_ih[j] + b_hh[j];
        } else if (g == 1) { // z (row H+j)
            v = w_ih[(size_t)(H + j) * H + k] + w_hh[(size_t)(H + j) * H + k];
            bb = b_ih[H + j] + b_hh[H + j];
        } else if (g == 2) { // i_n (row 2H+j of w_ih)
            v = w_ih[(size_t)(2 * H + j) * H + k];
            bb = b_ih[2 * H + j];
        } else {             // h_n (row 2H+j of w_hh)
            v = w_hh[(size_t)(2 * H + j) * H + k];
            bb = b_hh[2 * H + j];
        }
    }
    g_B[idx] = __float2half(v);
    if (k == 0) g_bias[n] = bb;
}

// ================= initial: x -> fp16 A (buffer 0) =================
__global__ __launch_bounds__(256) void convert_x_kernel(const float* __restrict__ x) {
    int idx = blockIdx.x * blockDim.x + threadIdx.x;   // over BB*H/4
    float4 v = *(const float4*)(x + (size_t)idx * 4);
    *(uint2*)(g_A0 + (size_t)idx * 4) = make_uint2(pkh2(v.x, v.y), pkh2(v.z, v.w));
}

// ===== mma.sync GEMM: heads -> GELU fp16 Yh; gates -> full GRU update in epilogue ====
__global__ __launch_bounds__(256, 2) void gemm_mma_kernel(int rb,
                                                          const float* __restrict__ hin,
                                                          float* __restrict__ hout) {
    extern __shared__ char smem[];
    uint32_t sb = smem_u32(smem);
    int tid = threadIdx.x;
    int lane = tid & 31;
    int wid = tid >> 5;
    int warp_m = wid & 1;     // 2 warps in M -> 64 rows each
    int warp_n = wid >> 1;    // 4 warps in N -> 32 cols each
    int m0 = blockIdx.y * BM;
    int n0 = blockIdx.x * BN;

    const __half* Ain = rb ? g_A1 : g_A0;
    __half* Aout = rb ? g_A0 : g_A1;

    // g2s: each thread covers rows row0+{0,32,64,96} at 16B unit u0, per array
    int row0 = tid >> 3;          // 0..31
    int u0 = tid & 7;
    uint32_t so0 = SW(row0, u0);
    uint32_t so1 = SW(row0 + 32, u0);
    uint32_t so2 = SW(row0 + 64, u0);
    uint32_t so3 = SW(row0 + 96, u0);
    const __half* pA0 = Ain + (size_t)(m0 + row0) * H + u0 * 8;
    const __half* pB0 = g_B + (size_t)(n0 + row0) * H + u0 * 8;

    // ldmatrix offset components
    uint32_t rA = (uint32_t)(warp_m * 64 + (lane & 15));
    uint32_t baseA = rA * 128u;
    uint32_t hib = (uint32_t)(lane >> 4);
    uint32_t mAx = rA & 7u;
    uint32_t rB = (uint32_t)(warp_n * 32 + (lane & 7) + ((lane >> 4) << 3));
    uint32_t baseB = rB * 128u;
    uint32_t bbit = (uint32_t)((lane >> 3) & 1);
    uint32_t mBx = rB & 7u;
    uint32_t xA[4], xB[4];
    #pragma unroll
    for (int ks = 0; ks < 4; ks++) {
        xA[ks] = (((uint32_t)(ks * 2) + hib) ^ mAx) << 4;
        xB[ks] = (((uint32_t)(ks * 2) + bbit) ^ mBx) << 4;
    }

    float acc[4][4][4];
    #pragma unroll
    for (int i = 0; i < 4; i++)
        #pragma unroll
        for (int j = 0; j < 4; j++)
            #pragma unroll
            for (int r = 0; r < 4; r++) acc[i][j][r] = 0.f;

    #define ISSUE(kb, stg) do {                                                   \
        uint32_t base = sb + (stg) * STAGE_B;                                     \
        int ko = (kb) * BK;                                                       \
        cpasync16(base + so0,          pA0 + ko);                                 \
        cpasync16(base + so1,          pA0 + (size_t)32 * H + ko);                \
        cpasync16(base + so2,          pA0 + (size_t)64 * H + ko);                \
        cpasync16(base + so3,          pA0 + (size_t)96 * H + ko);                \
        cpasync16(base + TILE_B + so0, pB0 + ko);                                 \
        cpasync16(base + TILE_B + so1, pB0 + (size_t)32 * H + ko);                \
        cpasync16(base + TILE_B + so2, pB0 + (size_t)64 * H + ko);                \
        cpasync16(base + TILE_B + so3, pB0 + (size_t)96 * H + ko);                \
        cp_commit();                                                              \
    } while (0)

    ISSUE(0, 0);
    ISSUE(1, 1);

    const int NKB = H / BK;   // 16
    for (int kb = 0; kb < NKB; kb++) {
        if (kb < NKB - 2) cp_wait1(); else cp_wait0();
        __syncthreads();

        uint32_t base = sb + (uint32_t)(kb % STAGES) * STAGE_B;
        uint32_t sA = base + baseA;
        uint32_t sB = base + TILE_B + baseB;

        #pragma unroll
        for (int ks = 0; ks < 4; ks++) {
            uint32_t Af[4][4], Bf[4][2];
            ldsm4(sB + xB[ks],         Bf[0][0], Bf[0][1], Bf[1][0], Bf[1][1]);
            ldsm4(sB + 2048 + xB[ks],  Bf[2][0], Bf[2][1], Bf[3][0], Bf[3][1]);
            #pragma unroll
            for (int mi = 0; mi < 4; mi++)
                ldsm4(sA + mi * 2048 + xA[ks], Af[mi][0], Af[mi][1], Af[mi][2], Af[mi][3]);
            #pragma unroll
            for (int mi = 0; mi < 4; mi++)
                #pragma unroll
                for (int nj = 0; nj < 4; nj++)
                    mma16816(acc[mi][nj], Af[mi], Bf[nj]);
        }
        __syncthreads();
        if (kb + 2 < NKB) ISSUE(kb + 2, (kb + 2) % STAGES);
    }

    if (n0 < 2048) {
        // ---- head epilogue: +bias, GELU, store fp16 to g_Yh ----
        #pragma unroll
        for (int nj = 0; nj < 4; nj++) {
            int n = n0 + warp_n * 32 + nj * 8 + (lane & 3) * 2;
            float2 b2 = *(const float2*)&g_bias[n];
            #pragma unroll
            for (int mi = 0; mi < 4; mi++) {
                int m = m0 + warp_m * 64 + mi * 16 + (lane >> 2);
                float v0 = gelu_f(acc[mi][nj][0] + b2.x);
                float v1 = gelu_f(acc[mi][nj][1] + b2.y);
                float v2 = gelu_f(acc[mi][nj][2] + b2.x);
                float v3 = gelu_f(acc[mi][nj][3] + b2.y);
                *(uint32_t*)(g_Yh + (size_t)m * 2048 + n) = pkh2(v0, v1);
                *(uint32_t*)(g_Yh + (size_t)(m + 8) * 2048 + n) = pkh2(v2, v3);
            }
        }
    } else {
        // ---- gate epilogue: full GRU update for 128 rows x 32 hidden units ----
        int j0g = (n0 - 2048) >> 2;                    // global j base (multiple of 32)
        float* sh_hold = (float*)smem;                  // [128][33]
        float* sh_hnew = (float*)(smem + 17024);        // [128][33]

        // stage h_old tile [128][32] coalesced
        __syncthreads();
        #pragma unroll
        for (int it = 0; it < 4; it++) {
            int i4 = tid + it * 256;        // 0..1023
            int r = i4 >> 3;
            int c4 = i4 & 7;
            float4 v = *(const float4*)(hin + (size_t)(m0 + r) * H + j0g + c4 * 4);
            float* d = &sh_hold[r * 33 + c4 * 4];
            d[0] = v.x; d[1] = v.y; d[2] = v.z; d[3] = v.w;
        }
        __syncthreads();

        int j_local = warp_n * 8 + ((lane & 3) >> 1);   // + nj*2 below
        bool compute = ((lane & 1) == 0);
        #pragma unroll
        for (int nj = 0; nj < 4; nj++) {
            int n = n0 + warp_n * 32 + nj * 8 + (lane & 3) * 2;
            float2 b2 = *(const float2*)&g_bias[n];
            #pragma unroll
            for (int mi = 0; mi < 4; mi++) {
                float c0 = acc[mi][nj][0] + b2.x;
                float c1 = acc[mi][nj][1] + b2.y;
                float c2 = acc[mi][nj][2] + b2.x;
                float c3 = acc[mi][nj][3] + b2.y;
                float p0 = __shfl_xor_sync(0xffffffffu, c0, 1);
                float p1 = __shfl_xor_sync(0xffffffffu, c1, 1);
                float p2 = __shfl_xor_sync(0xffffffffu, c2, 1);
                float p3 = __shfl_xor_sync(0xffffffffu, c3, 1);
                if (compute) {
                    int jl = j_local + nj * 2;
                    int ml = warp_m * 64 + mi * 16 + (lane >> 2);
                    // row ml: r=c0, z=c1, in=p0, hn=p1
                    float rr = sigmoid_f(c0);
                    float zz = sigmoid_f(c1);
                    float nn = tanhf(p0 + rr * p1);
                    sh_hnew[ml * 33 + jl] = (1.f - zz) * nn + zz * sh_hold[ml * 33 + jl];
                    // row ml+8
                    float rr2 = sigmoid_f(c2);
                    float zz2 = sigmoid_f(c3);
                    float nn2 = tanhf(p2 + rr2 * p3);
                    sh_hnew[(ml + 8) * 33 + jl] =
                        (1.f - zz2) * nn2 + zz2 * sh_hold[(ml + 8) * 33 + jl];
                }
            }
        }
        __syncthreads();

        // write h' fp32 + fp16 coalesced
        #pragma unroll
        for (int it = 0; it < 4; it++) {
            int i4 = tid + it * 256;        // 0..1023
            int r = i4 >> 3;
            int c4 = i4 & 7;
            const float* s = &sh_hnew[r * 33 + c4 * 4];
            float4 v = make_float4(s[0], s[1], s[2], s[3]);
            size_t off = (size_t)(m0 + r) * H + j0g + c4 * 4;
            *(float4*)(hout + off) = v;
            *(uint2*)(Aout + off) = make_uint2(pkh2(v.x, v.y), pkh2(v.z, v.w));
        }
    }
}

// ================= heads (reads fp16 GELU'd activations) =================
__global__ __launch_bounds__(256) void heads_kernel(
    const float* __restrict__ w_op2, const float* __restrict__ b_op2,
    const float* __restrict__ w_num2, const float* __restrict__ b_num2,
    float* __restrict__ ops, float* __restrict__ nums)
{
    __shared__ float s_w2[H * 5];
    __shared__ float s_wn[H];
    int tid = threadIdx.x;
    for (int i = tid; i < H * 5; i += 256) s_w2[i] = w_op2[i];
    for (int i = tid; i < H; i += 256)     s_wn[i] = w_num2[i];
    __syncthreads();

    int warp = tid >> 5, lane = tid & 31;
    int b = blockIdx.x * 8 + warp;
    const __half* Yr = g_Yh + (size_t)b * 2048;

    float a0 = 0.f, a1 = 0.f, a2 = 0.f, a3 = 0.f, a4 = 0.f, an = 0.f;
    #pragma unroll
    for (int it = 0; it < 8; it++) {
        int j = lane * 4 + it * 128;
        uint2 gp = *(const uint2*)(Yr + j);
        uint2 np = *(const uint2*)(Yr + 1024 + j);
        float2 g01 = __half22float2(*(const __half2*)&gp.x);
        float2 g23 = __half22float2(*(const __half2*)&gp.y);
        float2 n01 = __half22float2(*(const __half2*)&np.x);
        float2 n23 = __half22float2(*(const __half2*)&np.y);
        float gv[4] = {g01.x, g01.y, g23.x, g23.y};
        float nv[4] = {n01.x, n01.y, n23.x, n23.y};
        #pragma unroll
        for (int e = 0; e < 4; e++) {
            const float* w = &s_w2[(j + e) * 5];
            a0 += gv[e] * w[0];
            a1 += gv[e] * w[1];
            a2 += gv[e] * w[2];
            a3 += gv[e] * w[3];
            a4 += gv[e] * w[4];
            an += nv[e] * s_wn[j + e];
        }
    }
    #pragma unroll
    for (int off = 16; off > 0; off >>= 1) {
        a0 += __shfl_xor_sync(0xffffffffu, a0, off);
        a1 += __shfl_xor_sync(0xffffffffu, a1, off);
        a2 += __shfl_xor_sync(0xffffffffu, a2, off);
        a3 += __shfl_xor_sync(0xffffffffu, a3, off);
        a4 += __shfl_xor_sync(0xffffffffu, a4, off);
        an += __shfl_xor_sync(0xffffffffu, an, off);
    }
    if (lane == 0) {
        float* o = ops + (size_t)b * 5;
        o[0] = a0 + b_op2[0];
        o[1] = a1 + b_op2[1];
        o[2] = a2 + b_op2[2];
        o[3] = a3 + b_op2[3];
        o[4] = a4 + b_op2[4];
        nums[b] = an + b_num2[0];
    }
}

extern "C" void kernel_launch(void* const* d_in, const int* in_sizes, int n_in,
                              void* d_out, int out_size) {
    const float* x      = (const float*)d_in[0];
    const float* w_op1  = (const float*)d_in[2];
    const float* b_op1  = (const float*)d_in[3];
    const float* w_op2  = (const float*)d_in[4];
    const float* b_op2  = (const float*)d_in[5];
    const float* w_num1 = (const float*)d_in[6];
    const float* b_num1 = (const float*)d_in[7];
    const float* w_num2 = (const float*)d_in[8];
    const float* b_num2 = (const float*)d_in[9];
    const float* w_ih   = (const float*)d_in[10];
    const float* b_ih   = (const float*)d_in[11];
    const float* w_hh   = (const float*)d_in[12];
    const float* b_hh   = (const float*)d_in[13];

    float* out = (float*)d_out;
    float* final_state = out;                       // [B,H]
    float* ops    = out + (size_t)BB * H;           // [8,B,5]
    float* nums   = ops + (size_t)NSTEPS * BB * 5;  // [8,B,1]
    float* states = nums + (size_t)NSTEPS * BB;     // [8,B,H]

    cudaFuncSetAttribute(gemm_mma_kernel, cudaFuncAttributeMaxDynamicSharedMemorySize, GEMM_SMEM);

    prep_kernel<<<(NB * H + 255) / 256, 256>>>(w_op1, b_op1, w_num1, b_num1,
                                               w_ih, b_ih, w_hh, b_hh);
    convert_x_kernel<<<(BB * H / 4) / 256, 256>>>(x);
    cudaMemcpyAsync(states, x, (size_t)BB * H * sizeof(float), cudaMemcpyDeviceToDevice);

    for (int s = 0; s < NSTEPS; s++) {
        const float* h = states + (size_t)s * BB * H;
        float* hnext = (s < NSTEPS - 1) ? states + (size_t)(s + 1) * BB * H : final_state;

        dim3 grid(NB / BN, BB / BM);
        gemm_mma_kernel<<<grid, 256, GEMM_SMEM>>>(s & 1, h, hnext);
        heads_kernel<<<BB / 8, 256>>>(w_op2, b_op2, w_num2, b_num2,
                                      ops + (size_t)s * BB * 5, nums + (size_t)s * BB);
    }
}